// round 12
// baseline (speedup 1.0000x reference)
#include <cuda_runtime.h>
#include <cuda_bf16.h>
#include <cstdint>

// CausalAttention via mma.sync bf16 hi/lo-split (3-MMA emulated fp32).
// R12: back to the R10 128x128 CTA tile (32x64 warp tile), but BK=32 with
// 40-elem padded rows so smem = 2x40KB per CTA -> 2 CTAs/SM (16 warps/SM).
// Goal: cover sync/cp.async bubbles + HMMA latency with cross-CTA overlap.

typedef unsigned int u32;
typedef unsigned long long u64;

#define TPB 256
#define BK 32                    // K-chunk in bf16 elems
#define LDSS 40                  // padded smem row (80B) - conflict-free ldmatrix
#define TILE_B (128 * LDSS * 2)  // 10240 B : 128x32 bf16 tile
#define BUF_B (4 * TILE_B)       // Ah, Al, Bh, Bl = 40960
#define GEMM_SMEM (2 * BUF_B)    // double buffer = 81920 (2 CTAs -> 160KB/SM)

// ---------------- scratch (no allocation anywhere) ----------------
__device__ __nv_bfloat16 g_xh[8192 * 1024];
__device__ __nv_bfloat16 g_xl[8192 * 1024];
__device__ __nv_bfloat16 g_WTh[3 * 1024 * 1024];
__device__ __nv_bfloat16 g_WTl[3 * 1024 * 1024];
__device__ __nv_bfloat16 g_Qh[4 * 2048 * 1024];
__device__ __nv_bfloat16 g_Ql[4 * 2048 * 1024];
__device__ __nv_bfloat16 g_Kh[4 * 2048 * 1024];
__device__ __nv_bfloat16 g_Kl[4 * 2048 * 1024];
__device__ float         g_V[4 * 2048 * 1024];
__device__ __nv_bfloat16 g_VTh[(size_t)4 * 1024 * 2048];
__device__ __nv_bfloat16 g_VTl[(size_t)4 * 1024 * 2048];
__device__ float         g_S[(size_t)4 * 2048 * 2048];
__device__ __nv_bfloat16 g_Ph[(size_t)4 * 2048 * 2048];
__device__ __nv_bfloat16 g_Pl[(size_t)4 * 2048 * 2048];

// ---------------- helpers ----------------
__device__ __forceinline__ u32 smem_u32(const void* p) {
    u32 a;
    asm("{ .reg .u64 t; cvta.to.shared.u64 t, %1; cvt.u32.u64 %0, t; }"
        : "=r"(a) : "l"(p));
    return a;
}

__device__ __forceinline__ void cp_async16(u32 dst, const void* src) {
    asm volatile("cp.async.cg.shared.global [%0], [%1], 16;"
                 :: "r"(dst), "l"(src) : "memory");
}
#define CP_COMMIT() asm volatile("cp.async.commit_group;" ::: "memory")
#define CP_WAIT(N)  asm volatile("cp.async.wait_group %0;" :: "n"(N) : "memory")

__device__ __forceinline__ void ldmx4(u32 a, u32& r0, u32& r1, u32& r2, u32& r3) {
    asm volatile("ldmatrix.sync.aligned.m8n8.x4.shared.b16 {%0,%1,%2,%3}, [%4];"
                 : "=r"(r0), "=r"(r1), "=r"(r2), "=r"(r3) : "r"(a));
}

__device__ __forceinline__ void mma16816(float c[4], const u32 a[4], const u32 b[2]) {
    asm volatile(
        "mma.sync.aligned.m16n8k16.row.col.f32.bf16.bf16.f32 "
        "{%0,%1,%2,%3}, {%4,%5,%6,%7}, {%8,%9}, {%0,%1,%2,%3};"
        : "+f"(c[0]), "+f"(c[1]), "+f"(c[2]), "+f"(c[3])
        : "r"(a[0]), "r"(a[1]), "r"(a[2]), "r"(a[3]), "r"(b[0]), "r"(b[1]));
}

__device__ __forceinline__ void split2(float v, __nv_bfloat16& h, __nv_bfloat16& l) {
    h = __float2bfloat16_rn(v);
    l = __float2bfloat16_rn(v - __bfloat162float(h));
}

// ---------------- GEMM core ----------------
// C[128x128 tile at (m0,n0)] = sum_k A[m,k]*B[n,k], A/B hi+lo bf16, K-major.
// MODE 0: fp32 out (Cf) * scale.   MODE 1: split bf16 out (Ch, Cl).
template <int MODE>
__device__ __forceinline__ void gemm_core(
    const __nv_bfloat16* __restrict__ Ah, const __nv_bfloat16* __restrict__ Al, int lda,
    const __nv_bfloat16* __restrict__ Bh, const __nv_bfloat16* __restrict__ Bl, int ldb,
    int m0, int n0, int Klen, float scale,
    float* __restrict__ Cf, __nv_bfloat16* __restrict__ Ch, __nv_bfloat16* __restrict__ Cl,
    int ldc)
{
    extern __shared__ char smem[];
    const u32 sbase = smem_u32(smem);
    const int tid = threadIdx.x;
    const int wid = tid >> 5;
    const int lane = tid & 31;
    const int warp_m = (wid & 3) * 32;   // 4 warps over M
    const int warp_n = (wid >> 2) * 64;  // 2 warps over N

    // cp.async mapping: each thread loads one row-half (2x16B) per matrix.
    const int lrow = tid >> 1;            // 0..127
    const int lseg = (tid & 1) * 16;      // elem col 0 or 16
    const u32 dst_off = (u32)(lrow * LDSS + lseg) * 2;
    const __nv_bfloat16* pAh = Ah + (size_t)(m0 + lrow) * lda + lseg;
    const __nv_bfloat16* pAl = Al + (size_t)(m0 + lrow) * lda + lseg;
    const __nv_bfloat16* pBh = Bh + (size_t)(n0 + lrow) * ldb + lseg;
    const __nv_bfloat16* pBl = Bl + (size_t)(n0 + lrow) * ldb + lseg;

    const int nch = Klen / BK;

    // ldmatrix base offsets (within a tile)
    const u32 lm_a0 = (u32)((warp_m + (lane & 15)) * LDSS + (lane >> 4) * 8) * 2;
    const u32 lm_b0 = (u32)((warp_n + (lane & 15)) * LDSS + (lane >> 4) * 8) * 2;

    float acc[2][8][4];
#pragma unroll
    for (int i = 0; i < 2; ++i)
#pragma unroll
        for (int j = 0; j < 8; ++j)
#pragma unroll
            for (int q = 0; q < 4; ++q) acc[i][j][q] = 0.0f;

    // ---- prologue: load chunk 0 ----
    {
        const u32 d = sbase + dst_off;
        cp_async16(d + 0 * TILE_B,      pAh);
        cp_async16(d + 0 * TILE_B + 16, pAh + 8);
        cp_async16(d + 1 * TILE_B,      pAl);
        cp_async16(d + 1 * TILE_B + 16, pAl + 8);
        cp_async16(d + 2 * TILE_B,      pBh);
        cp_async16(d + 2 * TILE_B + 16, pBh + 8);
        cp_async16(d + 3 * TILE_B,      pBl);
        cp_async16(d + 3 * TILE_B + 16, pBl + 8);
        CP_COMMIT();
    }

    for (int c = 0; c < nch; ++c) {
        // issue loads for chunk c+1 into the other buffer
        if (c + 1 < nch) {
            const u32 d = sbase + ((c + 1) & 1) * BUF_B + dst_off;
            const int k0 = (c + 1) * BK;
            cp_async16(d + 0 * TILE_B,      pAh + k0);
            cp_async16(d + 0 * TILE_B + 16, pAh + k0 + 8);
            cp_async16(d + 1 * TILE_B,      pAl + k0);
            cp_async16(d + 1 * TILE_B + 16, pAl + k0 + 8);
            cp_async16(d + 2 * TILE_B,      pBh + k0);
            cp_async16(d + 2 * TILE_B + 16, pBh + k0 + 8);
            cp_async16(d + 3 * TILE_B,      pBl + k0);
            cp_async16(d + 3 * TILE_B + 16, pBl + k0 + 8);
            CP_COMMIT();
            CP_WAIT(1);   // chunk c complete, c+1 in flight
        } else {
            CP_WAIT(0);
        }
        __syncthreads();

        const u32 ba = sbase + (c & 1) * BUF_B;
        const u32 aAh = ba + lm_a0;
        const u32 aAl = ba + TILE_B + lm_a0;
        const u32 aBh = ba + 2 * TILE_B + lm_b0;
        const u32 aBl = ba + 3 * TILE_B + lm_b0;

#pragma unroll
        for (int ks = 0; ks < BK / 16; ++ks) {
            const u32 ko = (u32)(ks * 16) * 2;
            u32 bh[8][2], bl[8][2];
#pragma unroll
            for (int g = 0; g < 4; ++g) {   // 16 n-rows per ldmatrix.x4
                u32 r0, r1, r2, r3;
                ldmx4(aBh + ko + (u32)(g * 16 * LDSS) * 2, r0, r1, r2, r3);
                bh[2 * g][0] = r0; bh[2 * g][1] = r2;
                bh[2 * g + 1][0] = r1; bh[2 * g + 1][1] = r3;
                ldmx4(aBl + ko + (u32)(g * 16 * LDSS) * 2, r0, r1, r2, r3);
                bl[2 * g][0] = r0; bl[2 * g][1] = r2;
                bl[2 * g + 1][0] = r1; bl[2 * g + 1][1] = r3;
            }
#pragma unroll
            for (int mf = 0; mf < 2; ++mf) {
                u32 ah[4], al[4];
                ldmx4(aAh + ko + (u32)(mf * 16 * LDSS) * 2,
                      ah[0], ah[1], ah[2], ah[3]);
                ldmx4(aAl + ko + (u32)(mf * 16 * LDSS) * 2,
                      al[0], al[1], al[2], al[3]);
#pragma unroll
                for (int nf = 0; nf < 8; ++nf) {
                    mma16816(acc[mf][nf], ah, bh[nf]);
                    mma16816(acc[mf][nf], ah, bl[nf]);
                    mma16816(acc[mf][nf], al, bh[nf]);
                }
            }
        }
        __syncthreads();
    }

    // ---- epilogue ----
    const int erow = lane >> 2;
    const int ecol = (lane & 3) * 2;
#pragma unroll
    for (int mf = 0; mf < 2; ++mf) {
        const int rbase = m0 + warp_m + mf * 16 + erow;
#pragma unroll
        for (int nf = 0; nf < 8; ++nf) {
            const int ccol = n0 + warp_n + nf * 8 + ecol;
            if (MODE == 0) {
                float2 v0, v1;
                v0.x = acc[mf][nf][0] * scale; v0.y = acc[mf][nf][1] * scale;
                v1.x = acc[mf][nf][2] * scale; v1.y = acc[mf][nf][3] * scale;
                *(float2*)(Cf + (size_t)rbase * ldc + ccol) = v0;
                *(float2*)(Cf + (size_t)(rbase + 8) * ldc + ccol) = v1;
            } else {
                __nv_bfloat16 h0, l0, h1, l1;
                split2(acc[mf][nf][0], h0, l0);
                split2(acc[mf][nf][1], h1, l1);
                *(__nv_bfloat162*)(Ch + (size_t)rbase * ldc + ccol) = __halves2bfloat162(h0, h1);
                *(__nv_bfloat162*)(Cl + (size_t)rbase * ldc + ccol) = __halves2bfloat162(l0, l1);
                split2(acc[mf][nf][2], h0, l0);
                split2(acc[mf][nf][3], h1, l1);
                *(__nv_bfloat162*)(Ch + (size_t)(rbase + 8) * ldc + ccol) = __halves2bfloat162(h0, h1);
                *(__nv_bfloat162*)(Cl + (size_t)(rbase + 8) * ldc + ccol) = __halves2bfloat162(l0, l1);
            }
        }
    }
}

// ---------------- prep kernels ----------------
__global__ void split_x_kernel(const float* __restrict__ x) {
    const int n = 8192 * 1024;
    for (int i = blockIdx.x * blockDim.x + threadIdx.x; i < n; i += gridDim.x * blockDim.x) {
        __nv_bfloat16 h, l;
        split2(x[i], h, l);
        g_xh[i] = h; g_xl[i] = l;
    }
}

__global__ void wt_kernel(const float* __restrict__ Wq, const float* __restrict__ Wk,
                          const float* __restrict__ Wv) {
    __shared__ float t[32][33];
    const float* W = (blockIdx.z == 0) ? Wq : (blockIdx.z == 1) ? Wk : Wv;
    __nv_bfloat16* Th = g_WTh + (size_t)blockIdx.z * 1024 * 1024;
    __nv_bfloat16* Tl = g_WTl + (size_t)blockIdx.z * 1024 * 1024;
    const int n0 = blockIdx.x * 32, k0 = blockIdx.y * 32;
    const int tx = threadIdx.x, ty = threadIdx.y;
#pragma unroll
    for (int i = 0; i < 4; ++i)
        t[ty + i * 8][tx] = W[(size_t)(k0 + ty + i * 8) * 1024 + n0 + tx];
    __syncthreads();
#pragma unroll
    for (int i = 0; i < 4; ++i) {
        __nv_bfloat16 h, l;
        split2(t[tx][ty + i * 8], h, l);  // = W[k0+tx][n0+ty+i*8]
        const size_t o = (size_t)(n0 + ty + i * 8) * 1024 + k0 + tx;
        Th[o] = h; Tl[o] = l;
    }
}

__global__ void vt_kernel() {
    __shared__ float t[32][33];
    const int b = blockIdx.z;
    const float* V = g_V + (size_t)b * 2048 * 1024;
    __nv_bfloat16* Th = g_VTh + (size_t)b * 1024 * 2048;
    __nv_bfloat16* Tl = g_VTl + (size_t)b * 1024 * 2048;
    const int e0 = blockIdx.x * 32, k0 = blockIdx.y * 32;
    const int tx = threadIdx.x, ty = threadIdx.y;
#pragma unroll
    for (int i = 0; i < 4; ++i)
        t[ty + i * 8][tx] = V[(size_t)(k0 + ty + i * 8) * 1024 + e0 + tx];
    __syncthreads();
#pragma unroll
    for (int i = 0; i < 4; ++i) {
        __nv_bfloat16 h, l;
        split2(t[tx][ty + i * 8], h, l);  // = V[k0+tx][e0+ty+i*8]
        const size_t o = (size_t)(e0 + ty + i * 8) * 2048 + k0 + tx;
        Th[o] = h; Tl[o] = l;
    }
}

// ---------------- GEMM kernels ----------------
__global__ void __launch_bounds__(TPB, 2)
proj_kernel() {
    const int z = blockIdx.z;
    const int m0 = blockIdx.y * 128;
    const int n0 = blockIdx.x * 128;
    const __nv_bfloat16* Bh = g_WTh + (size_t)z * 1024 * 1024;
    const __nv_bfloat16* Bl = g_WTl + (size_t)z * 1024 * 1024;
    if (z == 0)
        gemm_core<1>(g_xh, g_xl, 1024, Bh, Bl, 1024, m0, n0, 1024, 1.0f,
                     nullptr, g_Qh, g_Ql, 1024);
    else if (z == 1)
        gemm_core<1>(g_xh, g_xl, 1024, Bh, Bl, 1024, m0, n0, 1024, 1.0f,
                     nullptr, g_Kh, g_Kl, 1024);
    else
        gemm_core<0>(g_xh, g_xl, 1024, Bh, Bl, 1024, m0, n0, 1024, 1.0f,
                     g_V, nullptr, nullptr, 1024);
}

__global__ void __launch_bounds__(TPB, 2)
score_kernel() {
    const int kb = blockIdx.x, qb = blockIdx.y, b = blockIdx.z;
    if (kb > qb) return;  // block fully above diagonal
    const size_t qo = (size_t)b * 2048 * 1024;
    gemm_core<0>(g_Qh + qo, g_Ql + qo, 1024, g_Kh + qo, g_Kl + qo, 1024,
                 qb * 128, kb * 128, 1024, 0.03125f,
                 g_S + (size_t)b * 2048 * 2048, nullptr, nullptr, 2048);
}

__global__ void __launch_bounds__(TPB, 2)
pv_kernel(float* __restrict__ out) {
    const int nb = blockIdx.x, qb = blockIdx.y, b = blockIdx.z;
    const size_t po = (size_t)b * 2048 * 2048;
    const size_t vo = (size_t)b * 1024 * 2048;
    gemm_core<0>(g_Ph + po, g_Pl + po, 2048, g_VTh + vo, g_VTl + vo, 2048,
                 qb * 128, nb * 128, (qb + 1) * 128, 1.0f,
                 out + (size_t)b * 2048 * 1024, nullptr, nullptr, 1024);
}

// ---------------- softmax ----------------
__global__ void softmax_kernel() {
    const int q = blockIdx.x, b = blockIdx.y;
    float* row = g_S + ((size_t)b * 2048 + q) * 2048;
    __nv_bfloat16* ph = g_Ph + ((size_t)b * 2048 + q) * 2048;
    __nv_bfloat16* pl = g_Pl + ((size_t)b * 2048 + q) * 2048;
    const int len = q + 1;
    const int tid = threadIdx.x;
    __shared__ float red[TPB];

    float m = -1e30f;
    for (int i = tid; i < len; i += TPB) m = fmaxf(m, row[i]);
    red[tid] = m;
    __syncthreads();
#pragma unroll
    for (int s = TPB / 2; s > 0; s >>= 1) {
        if (tid < s) red[tid] = fmaxf(red[tid], red[tid + s]);
        __syncthreads();
    }
    m = red[0];
    __syncthreads();

    float sum = 0.0f;
    for (int i = tid; i < len; i += TPB) {
        float e = __expf(row[i] - m);
        row[i] = e;
        sum += e;
    }
    red[tid] = sum;
    __syncthreads();
#pragma unroll
    for (int s = TPB / 2; s > 0; s >>= 1) {
        if (tid < s) red[tid] += red[tid + s];
        __syncthreads();
    }
    const float inv = 1.0f / red[0];
    __syncthreads();

    const __nv_bfloat16 z = __float2bfloat16(0.0f);
    for (int i = tid; i < len; i += TPB) {
        __nv_bfloat16 h, l;
        split2(row[i] * inv, h, l);
        ph[i] = h; pl[i] = l;
    }
    const int klim = ((q >> 7) + 1) << 7;  // zero up to 128-tile boundary
    for (int i = len + tid; i < klim; i += TPB) { ph[i] = z; pl[i] = z; }
}

// ---------------- launch ----------------
extern "C" void kernel_launch(void* const* d_in, const int* in_sizes, int n_in,
                              void* d_out, int out_size) {
    const float* x  = (const float*)d_in[0];
    const float* Wq = (const float*)d_in[1];
    const float* Wk = (const float*)d_in[2];
    const float* Wv = (const float*)d_in[3];
    float* out = (float*)d_out;

    cudaFuncSetAttribute(proj_kernel,  cudaFuncAttributeMaxDynamicSharedMemorySize, GEMM_SMEM);
    cudaFuncSetAttribute(score_kernel, cudaFuncAttributeMaxDynamicSharedMemorySize, GEMM_SMEM);
    cudaFuncSetAttribute(pv_kernel,    cudaFuncAttributeMaxDynamicSharedMemorySize, GEMM_SMEM);

    split_x_kernel<<<4096, 256>>>(x);
    wt_kernel<<<dim3(32, 32, 3), dim3(32, 8)>>>(Wq, Wk, Wv);
    proj_kernel<<<dim3(8, 64, 3), TPB, GEMM_SMEM>>>();
    vt_kernel<<<dim3(32, 64, 4), dim3(32, 8)>>>();
    score_kernel<<<dim3(16, 16, 4), TPB, GEMM_SMEM>>>();
    softmax_kernel<<<dim3(2048, 4), TPB>>>();
    pv_kernel<<<dim3(8, 16, 4), TPB, GEMM_SMEM>>>(out);
}

// round 13
// speedup vs baseline: 1.1341x; 1.1341x over previous
#include <cuda_runtime.h>
#include <cuda_fp16.h>
#include <cstdint>

// CausalAttention via mma.sync fp16 hi/lo-split (3-MMA emulated fp32).
// R13: R10 structure (best: 981us), but split in fp16 instead of bf16:
//   main term  Ah*Bh -> f32-accum HMMA (rt saturated at 16 cyc/SMSP in R10)
//   corrections Ah*Bl, Al*Bh -> f16-accum HMMA (2 regs, possibly 2x rate)
// fp16 split covers 22 mantissa bits; dropped al*bl term is 2^-22.

typedef unsigned int u32;
typedef unsigned long long u64;

#define TPB 256
#define BK 64                 // K-chunk in fp16 elems
#define LDSS 72               // padded smem row (144B) - conflict-free ldmatrix
#define TILE_B (128 * LDSS * 2)          // 18432 B per 128x64 fp16 tile
#define BUF_B (4 * TILE_B)               // Ah, Al, Bh, Bl
#define GEMM_SMEM (2 * BUF_B)            // double buffer = 147456 B

// ---------------- scratch (no allocation anywhere) ----------------
__device__ __half g_xh[8192 * 1024];
__device__ __half g_xl[8192 * 1024];
__device__ __half g_WTh[3 * 1024 * 1024];
__device__ __half g_WTl[3 * 1024 * 1024];
__device__ __half g_Qh[4 * 2048 * 1024];
__device__ __half g_Ql[4 * 2048 * 1024];
__device__ __half g_Kh[4 * 2048 * 1024];
__device__ __half g_Kl[4 * 2048 * 1024];
__device__ float  g_V[4 * 2048 * 1024];
__device__ __half g_VTh[(size_t)4 * 1024 * 2048];
__device__ __half g_VTl[(size_t)4 * 1024 * 2048];
__device__ float  g_S[(size_t)4 * 2048 * 2048];
__device__ __half g_Ph[(size_t)4 * 2048 * 2048];
__device__ __half g_Pl[(size_t)4 * 2048 * 2048];

// ---------------- helpers ----------------
__device__ __forceinline__ u32 smem_u32(const void* p) {
    u32 a;
    asm("{ .reg .u64 t; cvta.to.shared.u64 t, %1; cvt.u32.u64 %0, t; }"
        : "=r"(a) : "l"(p));
    return a;
}

__device__ __forceinline__ void cp_async16(u32 dst, const void* src) {
    asm volatile("cp.async.cg.shared.global [%0], [%1], 16;"
                 :: "r"(dst), "l"(src) : "memory");
}
#define CP_COMMIT() asm volatile("cp.async.commit_group;" ::: "memory")
#define CP_WAIT(N)  asm volatile("cp.async.wait_group %0;" :: "n"(N) : "memory")

__device__ __forceinline__ void ldmx4(u32 a, u32& r0, u32& r1, u32& r2, u32& r3) {
    asm volatile("ldmatrix.sync.aligned.m8n8.x4.shared.b16 {%0,%1,%2,%3}, [%4];"
                 : "=r"(r0), "=r"(r1), "=r"(r2), "=r"(r3) : "r"(a));
}

// main term: f16 inputs, f32 accumulate
__device__ __forceinline__ void mma_f32(float c[4], const u32 a[4], const u32 b[2]) {
    asm volatile(
        "mma.sync.aligned.m16n8k16.row.col.f32.f16.f16.f32 "
        "{%0,%1,%2,%3}, {%4,%5,%6,%7}, {%8,%9}, {%0,%1,%2,%3};"
        : "+f"(c[0]), "+f"(c[1]), "+f"(c[2]), "+f"(c[3])
        : "r"(a[0]), "r"(a[1]), "r"(a[2]), "r"(a[3]), "r"(b[0]), "r"(b[1]));
}

// correction terms: f16 inputs, f16 accumulate (2 regs of f16x2)
__device__ __forceinline__ void mma_f16(u32 c[2], const u32 a[4], const u32 b[2]) {
    asm volatile(
        "mma.sync.aligned.m16n8k16.row.col.f16.f16.f16.f16 "
        "{%0,%1}, {%2,%3,%4,%5}, {%6,%7}, {%0,%1};"
        : "+r"(c[0]), "+r"(c[1])
        : "r"(a[0]), "r"(a[1]), "r"(a[2]), "r"(a[3]), "r"(b[0]), "r"(b[1]));
}

__device__ __forceinline__ void split2(float v, __half& h, __half& l) {
    h = __float2half_rn(v);
    l = __float2half_rn(v - __half2float(h));
}

// ---------------- GEMM core ----------------
// C[128x128 tile at (m0,n0)] = sum_k A[m,k]*B[n,k], A/B hi+lo fp16, K-major.
// MODE 0: fp32 out (Cf) * scale.   MODE 1: split fp16 out (Ch, Cl).
template <int MODE>
__device__ __forceinline__ void gemm_core(
    const __half* __restrict__ Ah, const __half* __restrict__ Al, int lda,
    const __half* __restrict__ Bh, const __half* __restrict__ Bl, int ldb,
    int m0, int n0, int Klen, float scale,
    float* __restrict__ Cf, __half* __restrict__ Ch, __half* __restrict__ Cl,
    int ldc)
{
    extern __shared__ char smem[];
    const u32 sbase = smem_u32(smem);
    const int tid = threadIdx.x;
    const int wid = tid >> 5;
    const int lane = tid & 31;
    const int warp_m = (wid & 3) * 32;   // 4 warps over M
    const int warp_n = (wid >> 2) * 64;  // 2 warps over N

    // cp.async mapping: 32 rows x 8 segs(16B) per pass, 4 passes per tile
    const int lrow = tid >> 3;            // 0..31
    const int lseg = (tid & 7) * 8;       // elem col 0..56
    const u32 dst_off = (u32)(lrow * LDSS + lseg) * 2;
    const __half* pAh = Ah + (size_t)(m0 + lrow) * lda + lseg;
    const __half* pAl = Al + (size_t)(m0 + lrow) * lda + lseg;
    const __half* pBh = Bh + (size_t)(n0 + lrow) * ldb + lseg;
    const __half* pBl = Bl + (size_t)(n0 + lrow) * ldb + lseg;

    const int nch = Klen / BK;

    // ldmatrix base offsets (within a tile)
    const u32 lm_a0 = (u32)((warp_m + (lane & 15)) * LDSS + (lane >> 4) * 8) * 2;
    const u32 lm_b0 = (u32)((warp_n + (lane & 15)) * LDSS + (lane >> 4) * 8) * 2;

    float acc[2][8][4];     // main f32 accumulators
    u32 cacc[2][8][2];      // correction f16x2 accumulators
#pragma unroll
    for (int i = 0; i < 2; ++i)
#pragma unroll
        for (int j = 0; j < 8; ++j) {
#pragma unroll
            for (int q = 0; q < 4; ++q) acc[i][j][q] = 0.0f;
            cacc[i][j][0] = 0u; cacc[i][j][1] = 0u;
        }

    // ---- prologue: load chunk 0 ----
    {
        const u32 ba = sbase;
#pragma unroll
        for (int p = 0; p < 4; ++p) {
            const u32 d = ba + dst_off + (u32)(32 * p * LDSS) * 2;
            cp_async16(d + 0 * TILE_B, pAh + (size_t)(32 * p) * lda);
            cp_async16(d + 1 * TILE_B, pAl + (size_t)(32 * p) * lda);
            cp_async16(d + 2 * TILE_B, pBh + (size_t)(32 * p) * ldb);
            cp_async16(d + 3 * TILE_B, pBl + (size_t)(32 * p) * ldb);
        }
        CP_COMMIT();
    }

    for (int c = 0; c < nch; ++c) {
        // issue loads for chunk c+1 into the other buffer
        if (c + 1 < nch) {
            const u32 ba = sbase + ((c + 1) & 1) * BUF_B;
            const int k0 = (c + 1) * BK;
#pragma unroll
            for (int p = 0; p < 4; ++p) {
                const u32 d = ba + dst_off + (u32)(32 * p * LDSS) * 2;
                cp_async16(d + 0 * TILE_B, pAh + (size_t)(32 * p) * lda + k0);
                cp_async16(d + 1 * TILE_B, pAl + (size_t)(32 * p) * lda + k0);
                cp_async16(d + 2 * TILE_B, pBh + (size_t)(32 * p) * ldb + k0);
                cp_async16(d + 3 * TILE_B, pBl + (size_t)(32 * p) * ldb + k0);
            }
            CP_COMMIT();
            CP_WAIT(1);   // chunk c complete, c+1 in flight
        } else {
            CP_WAIT(0);
        }
        __syncthreads();

        const u32 ba = sbase + (c & 1) * BUF_B;
        const u32 aAh = ba + lm_a0;
        const u32 aAl = ba + TILE_B + lm_a0;
        const u32 aBh = ba + 2 * TILE_B + lm_b0;
        const u32 aBl = ba + 3 * TILE_B + lm_b0;

#pragma unroll
        for (int ks = 0; ks < BK / 16; ++ks) {
            const u32 ko = (u32)(ks * 16) * 2;
            u32 bh[8][2], bl[8][2];
#pragma unroll
            for (int g = 0; g < 4; ++g) {   // 16 n-rows per ldmatrix.x4
                u32 r0, r1, r2, r3;
                ldmx4(aBh + ko + (u32)(g * 16 * LDSS) * 2, r0, r1, r2, r3);
                bh[2 * g][0] = r0; bh[2 * g][1] = r2;
                bh[2 * g + 1][0] = r1; bh[2 * g + 1][1] = r3;
                ldmx4(aBl + ko + (u32)(g * 16 * LDSS) * 2, r0, r1, r2, r3);
                bl[2 * g][0] = r0; bl[2 * g][1] = r2;
                bl[2 * g + 1][0] = r1; bl[2 * g + 1][1] = r3;
            }
#pragma unroll
            for (int mf = 0; mf < 2; ++mf) {
                u32 ah[4], al[4];
                ldmx4(aAh + ko + (u32)(mf * 16 * LDSS) * 2,
                      ah[0], ah[1], ah[2], ah[3]);
                ldmx4(aAl + ko + (u32)(mf * 16 * LDSS) * 2,
                      al[0], al[1], al[2], al[3]);
#pragma unroll
                for (int nf = 0; nf < 8; ++nf) {
                    mma_f32(acc[mf][nf], ah, bh[nf]);   // main (f32 accum)
                    mma_f16(cacc[mf][nf], ah, bl[nf]);  // corr 1 (f16 accum)
                    mma_f16(cacc[mf][nf], al, bh[nf]);  // corr 2 (f16 accum)
                }
            }
        }
        __syncthreads();
    }

    // ---- epilogue: combine main + corrections ----
    const int erow = lane >> 2;
    const int ecol = (lane & 3) * 2;
#pragma unroll
    for (int mf = 0; mf < 2; ++mf) {
        const int rbase = m0 + warp_m + mf * 16 + erow;
#pragma unroll
        for (int nf = 0; nf < 8; ++nf) {
            const int ccol = n0 + warp_n + nf * 8 + ecol;
            float2 c01 = __half22float2(*(__half2*)&cacc[mf][nf][0]);
            float2 c23 = __half22float2(*(__half2*)&cacc[mf][nf][1]);
            float v0 = acc[mf][nf][0] + c01.x;
            float v1 = acc[mf][nf][1] + c01.y;
            float v2 = acc[mf][nf][2] + c23.x;
            float v3 = acc[mf][nf][3] + c23.y;
            if (MODE == 0) {
                float2 w0, w1;
                w0.x = v0 * scale; w0.y = v1 * scale;
                w1.x = v2 * scale; w1.y = v3 * scale;
                *(float2*)(Cf + (size_t)rbase * ldc + ccol) = w0;
                *(float2*)(Cf + (size_t)(rbase + 8) * ldc + ccol) = w1;
            } else {
                __half h0, l0, h1, l1;
                split2(v0, h0, l0);
                split2(v1, h1, l1);
                *(__half2*)(Ch + (size_t)rbase * ldc + ccol) = __halves2half2(h0, h1);
                *(__half2*)(Cl + (size_t)rbase * ldc + ccol) = __halves2half2(l0, l1);
                split2(v2, h0, l0);
                split2(v3, h1, l1);
                *(__half2*)(Ch + (size_t)(rbase + 8) * ldc + ccol) = __halves2half2(h0, h1);
                *(__half2*)(Cl + (size_t)(rbase + 8) * ldc + ccol) = __halves2half2(l0, l1);
            }
        }
    }
}

// ---------------- prep kernels ----------------
__global__ void split_x_kernel(const float* __restrict__ x) {
    const int n = 8192 * 1024;
    for (int i = blockIdx.x * blockDim.x + threadIdx.x; i < n; i += gridDim.x * blockDim.x) {
        __half h, l;
        split2(x[i], h, l);
        g_xh[i] = h; g_xl[i] = l;
    }
}

__global__ void wt_kernel(const float* __restrict__ Wq, const float* __restrict__ Wk,
                          const float* __restrict__ Wv) {
    __shared__ float t[32][33];
    const float* W = (blockIdx.z == 0) ? Wq : (blockIdx.z == 1) ? Wk : Wv;
    __half* Th = g_WTh + (size_t)blockIdx.z * 1024 * 1024;
    __half* Tl = g_WTl + (size_t)blockIdx.z * 1024 * 1024;
    const int n0 = blockIdx.x * 32, k0 = blockIdx.y * 32;
    const int tx = threadIdx.x, ty = threadIdx.y;
#pragma unroll
    for (int i = 0; i < 4; ++i)
        t[ty + i * 8][tx] = W[(size_t)(k0 + ty + i * 8) * 1024 + n0 + tx];
    __syncthreads();
#pragma unroll
    for (int i = 0; i < 4; ++i) {
        __half h, l;
        split2(t[tx][ty + i * 8], h, l);  // = W[k0+tx][n0+ty+i*8]
        const size_t o = (size_t)(n0 + ty + i * 8) * 1024 + k0 + tx;
        Th[o] = h; Tl[o] = l;
    }
}

__global__ void vt_kernel() {
    __shared__ float t[32][33];
    const int b = blockIdx.z;
    const float* V = g_V + (size_t)b * 2048 * 1024;
    __half* Th = g_VTh + (size_t)b * 1024 * 2048;
    __half* Tl = g_VTl + (size_t)b * 1024 * 2048;
    const int e0 = blockIdx.x * 32, k0 = blockIdx.y * 32;
    const int tx = threadIdx.x, ty = threadIdx.y;
#pragma unroll
    for (int i = 0; i < 4; ++i)
        t[ty + i * 8][tx] = V[(size_t)(k0 + ty + i * 8) * 1024 + e0 + tx];
    __syncthreads();
#pragma unroll
    for (int i = 0; i < 4; ++i) {
        __half h, l;
        split2(t[tx][ty + i * 8], h, l);  // = V[k0+tx][e0+ty+i*8]
        const size_t o = (size_t)(e0 + ty + i * 8) * 2048 + k0 + tx;
        Th[o] = h; Tl[o] = l;
    }
}

// ---------------- GEMM kernels ----------------
__global__ void __launch_bounds__(TPB, 1)
proj_kernel() {
    const int z = blockIdx.z;
    const int m0 = blockIdx.y * 128;
    const int n0 = blockIdx.x * 128;
    const __half* Bh = g_WTh + (size_t)z * 1024 * 1024;
    const __half* Bl = g_WTl + (size_t)z * 1024 * 1024;
    if (z == 0)
        gemm_core<1>(g_xh, g_xl, 1024, Bh, Bl, 1024, m0, n0, 1024, 1.0f,
                     nullptr, g_Qh, g_Ql, 1024);
    else if (z == 1)
        gemm_core<1>(g_xh, g_xl, 1024, Bh, Bl, 1024, m0, n0, 1024, 1.0f,
                     nullptr, g_Kh, g_Kl, 1024);
    else
        gemm_core<0>(g_xh, g_xl, 1024, Bh, Bl, 1024, m0, n0, 1024, 1.0f,
                     g_V, nullptr, nullptr, 1024);
}

__global__ void __launch_bounds__(TPB, 1)
score_kernel() {
    const int kb = blockIdx.x, qb = blockIdx.y, b = blockIdx.z;
    if (kb > qb) return;
    const size_t qo = (size_t)b * 2048 * 1024;
    gemm_core<0>(g_Qh + qo, g_Ql + qo, 1024, g_Kh + qo, g_Kl + qo, 1024,
                 qb * 128, kb * 128, 1024, 0.03125f,
                 g_S + (size_t)b * 2048 * 2048, nullptr, nullptr, 2048);
}

__global__ void __launch_bounds__(TPB, 1)
pv_kernel(float* __restrict__ out) {
    const int nb = blockIdx.x, qb = blockIdx.y, b = blockIdx.z;
    const size_t po = (size_t)b * 2048 * 2048;
    const size_t vo = (size_t)b * 1024 * 2048;
    gemm_core<0>(g_Ph + po, g_Pl + po, 2048, g_VTh + vo, g_VTl + vo, 2048,
                 qb * 128, nb * 128, (qb + 1) * 128, 1.0f,
                 out + (size_t)b * 2048 * 1024, nullptr, nullptr, 1024);
}

// ---------------- softmax ----------------
__global__ void softmax_kernel() {
    const int q = blockIdx.x, b = blockIdx.y;
    float* row = g_S + ((size_t)b * 2048 + q) * 2048;
    __half* ph = g_Ph + ((size_t)b * 2048 + q) * 2048;
    __half* pl = g_Pl + ((size_t)b * 2048 + q) * 2048;
    const int len = q + 1;
    const int tid = threadIdx.x;
    __shared__ float red[TPB];

    float m = -1e30f;
    for (int i = tid; i < len; i += TPB) m = fmaxf(m, row[i]);
    red[tid] = m;
    __syncthreads();
#pragma unroll
    for (int s = TPB / 2; s > 0; s >>= 1) {
        if (tid < s) red[tid] = fmaxf(red[tid], red[tid + s]);
        __syncthreads();
    }
    m = red[0];
    __syncthreads();

    float sum = 0.0f;
    for (int i = tid; i < len; i += TPB) {
        float e = __expf(row[i] - m);
        row[i] = e;
        sum += e;
    }
    red[tid] = sum;
    __syncthreads();
#pragma unroll
    for (int s = TPB / 2; s > 0; s >>= 1) {
        if (tid < s) red[tid] += red[tid + s];
        __syncthreads();
    }
    const float inv = 1.0f / red[0];
    __syncthreads();

    const __half z = __float2half(0.0f);
    for (int i = tid; i < len; i += TPB) {
        __half h, l;
        split2(row[i] * inv, h, l);
        ph[i] = h; pl[i] = l;
    }
    const int klim = ((q >> 7) + 1) << 7;  // zero up to 128-tile boundary
    for (int i = len + tid; i < klim; i += TPB) { ph[i] = z; pl[i] = z; }
}

// ---------------- launch ----------------
extern "C" void kernel_launch(void* const* d_in, const int* in_sizes, int n_in,
                              void* d_out, int out_size) {
    const float* x  = (const float*)d_in[0];
    const float* Wq = (const float*)d_in[1];
    const float* Wk = (const float*)d_in[2];
    const float* Wv = (const float*)d_in[3];
    float* out = (float*)d_out;

    cudaFuncSetAttribute(proj_kernel,  cudaFuncAttributeMaxDynamicSharedMemorySize, GEMM_SMEM);
    cudaFuncSetAttribute(score_kernel, cudaFuncAttributeMaxDynamicSharedMemorySize, GEMM_SMEM);
    cudaFuncSetAttribute(pv_kernel,    cudaFuncAttributeMaxDynamicSharedMemorySize, GEMM_SMEM);

    split_x_kernel<<<4096, 256>>>(x);
    wt_kernel<<<dim3(32, 32, 3), dim3(32, 8)>>>(Wq, Wk, Wv);
    proj_kernel<<<dim3(8, 64, 3), TPB, GEMM_SMEM>>>();
    vt_kernel<<<dim3(32, 64, 4), dim3(32, 8)>>>();
    score_kernel<<<dim3(16, 16, 4), TPB, GEMM_SMEM>>>();
    softmax_kernel<<<dim3(2048, 4), TPB>>>();
    pv_kernel<<<dim3(8, 16, 4), TPB, GEMM_SMEM>>>(out);
}

// round 14
// speedup vs baseline: 1.6174x; 1.4261x over previous
#include <cuda_runtime.h>
#include <cuda_fp16.h>
#include <cstdint>

// CausalAttention via mma.sync fp16 asymmetric split (2-MMA emulated fp32).
// R14: A-side plain fp16 (Ah), B-side hi/lo split (Bh + Bl):
//   C = Ah*Bh (f32 accum) + Ah*Bl (f16 accum)  ==  Ah * B_exact
// HMMA count drops to 2/3 of R13 (pipe-saturated), smem to 3 tiles/buffer.

typedef unsigned int u32;
typedef unsigned long long u64;

#define TPB 256
#define BK 64                 // K-chunk in fp16 elems
#define LDSS 72               // padded smem row (144B) - conflict-free ldmatrix
#define TILE_B (128 * LDSS * 2)          // 18432 B per 128x64 fp16 tile
#define OFF_A 0
#define OFF_BH TILE_B
#define OFF_BL (2 * TILE_B)
#define BUF_B (3 * TILE_B)               // A, Bh, Bl = 55296
#define GEMM_SMEM (2 * BUF_B)            // double buffer = 110592 B

// ---------------- scratch (no allocation anywhere) ----------------
__device__ __half g_xh[8192 * 1024];
__device__ __half g_WTh[3 * 1024 * 1024];
__device__ __half g_WTl[3 * 1024 * 1024];
__device__ __half g_Qh[4 * 2048 * 1024];
__device__ __half g_Kh[4 * 2048 * 1024];
__device__ __half g_Kl[4 * 2048 * 1024];
__device__ float  g_V[4 * 2048 * 1024];
__device__ __half g_VTh[(size_t)4 * 1024 * 2048];
__device__ __half g_VTl[(size_t)4 * 1024 * 2048];
__device__ float  g_S[(size_t)4 * 2048 * 2048];
__device__ __half g_Ph[(size_t)4 * 2048 * 2048];

// ---------------- helpers ----------------
__device__ __forceinline__ u32 smem_u32(const void* p) {
    u32 a;
    asm("{ .reg .u64 t; cvta.to.shared.u64 t, %1; cvt.u32.u64 %0, t; }"
        : "=r"(a) : "l"(p));
    return a;
}

__device__ __forceinline__ void cp_async16(u32 dst, const void* src) {
    asm volatile("cp.async.cg.shared.global [%0], [%1], 16;"
                 :: "r"(dst), "l"(src) : "memory");
}
#define CP_COMMIT() asm volatile("cp.async.commit_group;" ::: "memory")
#define CP_WAIT(N)  asm volatile("cp.async.wait_group %0;" :: "n"(N) : "memory")

__device__ __forceinline__ void ldmx4(u32 a, u32& r0, u32& r1, u32& r2, u32& r3) {
    asm volatile("ldmatrix.sync.aligned.m8n8.x4.shared.b16 {%0,%1,%2,%3}, [%4];"
                 : "=r"(r0), "=r"(r1), "=r"(r2), "=r"(r3) : "r"(a));
}

// main term: f16 inputs, f32 accumulate
__device__ __forceinline__ void mma_f32(float c[4], const u32 a[4], const u32 b[2]) {
    asm volatile(
        "mma.sync.aligned.m16n8k16.row.col.f32.f16.f16.f32 "
        "{%0,%1,%2,%3}, {%4,%5,%6,%7}, {%8,%9}, {%0,%1,%2,%3};"
        : "+f"(c[0]), "+f"(c[1]), "+f"(c[2]), "+f"(c[3])
        : "r"(a[0]), "r"(a[1]), "r"(a[2]), "r"(a[3]), "r"(b[0]), "r"(b[1]));
}

// correction term: f16 inputs, f16 accumulate (2 regs of f16x2)
__device__ __forceinline__ void mma_f16(u32 c[2], const u32 a[4], const u32 b[2]) {
    asm volatile(
        "mma.sync.aligned.m16n8k16.row.col.f16.f16.f16.f16 "
        "{%0,%1}, {%2,%3,%4,%5}, {%6,%7}, {%0,%1};"
        : "+r"(c[0]), "+r"(c[1])
        : "r"(a[0]), "r"(a[1]), "r"(a[2]), "r"(a[3]), "r"(b[0]), "r"(b[1]));
}

__device__ __forceinline__ void split2(float v, __half& h, __half& l) {
    h = __float2half_rn(v);
    l = __float2half_rn(v - __half2float(h));
}

// ---------------- GEMM core ----------------
// C[128x128 tile at (m0,n0)] = sum_k A[m,k]*B[n,k]; A fp16, B hi+lo fp16.
// MODE 0: fp32 out (Cf)*scale.  MODE 1: split fp16 out (Ch,Cl).  MODE 2: Ch only.
template <int MODE>
__device__ __forceinline__ void gemm_core(
    const __half* __restrict__ A, int lda,
    const __half* __restrict__ Bh, const __half* __restrict__ Bl, int ldb,
    int m0, int n0, int Klen, float scale,
    float* __restrict__ Cf, __half* __restrict__ Ch, __half* __restrict__ Cl,
    int ldc)
{
    extern __shared__ char smem[];
    const u32 sbase = smem_u32(smem);
    const int tid = threadIdx.x;
    const int wid = tid >> 5;
    const int lane = tid & 31;
    const int warp_m = (wid & 3) * 32;   // 4 warps over M
    const int warp_n = (wid >> 2) * 64;  // 2 warps over N

    // cp.async mapping: 32 rows x 8 segs(16B) per pass, 4 passes per tile
    const int lrow = tid >> 3;            // 0..31
    const int lseg = (tid & 7) * 8;       // elem col 0..56
    const u32 dst_off = (u32)(lrow * LDSS + lseg) * 2;
    const __half* pA  = A  + (size_t)(m0 + lrow) * lda + lseg;
    const __half* pBh = Bh + (size_t)(n0 + lrow) * ldb + lseg;
    const __half* pBl = Bl + (size_t)(n0 + lrow) * ldb + lseg;

    const int nch = Klen / BK;

    // ldmatrix base offsets (within a tile)
    const u32 lm_a0 = (u32)((warp_m + (lane & 15)) * LDSS + (lane >> 4) * 8) * 2;
    const u32 lm_b0 = (u32)((warp_n + (lane & 15)) * LDSS + (lane >> 4) * 8) * 2;

    float acc[2][8][4];     // main f32 accumulators
    u32 cacc[2][8][2];      // correction f16x2 accumulators
#pragma unroll
    for (int i = 0; i < 2; ++i)
#pragma unroll
        for (int j = 0; j < 8; ++j) {
#pragma unroll
            for (int q = 0; q < 4; ++q) acc[i][j][q] = 0.0f;
            cacc[i][j][0] = 0u; cacc[i][j][1] = 0u;
        }

    // ---- prologue: load chunk 0 ----
    {
        const u32 ba = sbase;
#pragma unroll
        for (int p = 0; p < 4; ++p) {
            const u32 d = ba + dst_off + (u32)(32 * p * LDSS) * 2;
            cp_async16(d + OFF_A,  pA  + (size_t)(32 * p) * lda);
            cp_async16(d + OFF_BH, pBh + (size_t)(32 * p) * ldb);
            cp_async16(d + OFF_BL, pBl + (size_t)(32 * p) * ldb);
        }
        CP_COMMIT();
    }

    for (int c = 0; c < nch; ++c) {
        // issue loads for chunk c+1 into the other buffer
        if (c + 1 < nch) {
            const u32 ba = sbase + ((c + 1) & 1) * BUF_B;
            const int k0 = (c + 1) * BK;
#pragma unroll
            for (int p = 0; p < 4; ++p) {
                const u32 d = ba + dst_off + (u32)(32 * p * LDSS) * 2;
                cp_async16(d + OFF_A,  pA  + (size_t)(32 * p) * lda + k0);
                cp_async16(d + OFF_BH, pBh + (size_t)(32 * p) * ldb + k0);
                cp_async16(d + OFF_BL, pBl + (size_t)(32 * p) * ldb + k0);
            }
            CP_COMMIT();
            CP_WAIT(1);   // chunk c complete, c+1 in flight
        } else {
            CP_WAIT(0);
        }
        __syncthreads();

        const u32 ba = sbase + (c & 1) * BUF_B;
        const u32 aA  = ba + OFF_A  + lm_a0;
        const u32 aBh = ba + OFF_BH + lm_b0;
        const u32 aBl = ba + OFF_BL + lm_b0;

#pragma unroll
        for (int ks = 0; ks < BK / 16; ++ks) {
            const u32 ko = (u32)(ks * 16) * 2;
            u32 bh[8][2], bl[8][2];
#pragma unroll
            for (int g = 0; g < 4; ++g) {   // 16 n-rows per ldmatrix.x4
                u32 r0, r1, r2, r3;
                ldmx4(aBh + ko + (u32)(g * 16 * LDSS) * 2, r0, r1, r2, r3);
                bh[2 * g][0] = r0; bh[2 * g][1] = r2;
                bh[2 * g + 1][0] = r1; bh[2 * g + 1][1] = r3;
                ldmx4(aBl + ko + (u32)(g * 16 * LDSS) * 2, r0, r1, r2, r3);
                bl[2 * g][0] = r0; bl[2 * g][1] = r2;
                bl[2 * g + 1][0] = r1; bl[2 * g + 1][1] = r3;
            }
#pragma unroll
            for (int mf = 0; mf < 2; ++mf) {
                u32 ah[4];
                ldmx4(aA + ko + (u32)(mf * 16 * LDSS) * 2,
                      ah[0], ah[1], ah[2], ah[3]);
#pragma unroll
                for (int nf = 0; nf < 8; ++nf) {
                    mma_f32(acc[mf][nf], ah, bh[nf]);   // main (f32 accum)
                    mma_f16(cacc[mf][nf], ah, bl[nf]);  // correction (f16 accum)
                }
            }
        }
        __syncthreads();
    }

    // ---- epilogue: combine main + correction ----
    const int erow = lane >> 2;
    const int ecol = (lane & 3) * 2;
#pragma unroll
    for (int mf = 0; mf < 2; ++mf) {
        const int rbase = m0 + warp_m + mf * 16 + erow;
#pragma unroll
        for (int nf = 0; nf < 8; ++nf) {
            const int ccol = n0 + warp_n + nf * 8 + ecol;
            float2 c01 = __half22float2(*(__half2*)&cacc[mf][nf][0]);
            float2 c23 = __half22float2(*(__half2*)&cacc[mf][nf][1]);
            float v0 = acc[mf][nf][0] + c01.x;
            float v1 = acc[mf][nf][1] + c01.y;
            float v2 = acc[mf][nf][2] + c23.x;
            float v3 = acc[mf][nf][3] + c23.y;
            if (MODE == 0) {
                float2 w0, w1;
                w0.x = v0 * scale; w0.y = v1 * scale;
                w1.x = v2 * scale; w1.y = v3 * scale;
                *(float2*)(Cf + (size_t)rbase * ldc + ccol) = w0;
                *(float2*)(Cf + (size_t)(rbase + 8) * ldc + ccol) = w1;
            } else if (MODE == 1) {
                __half h0, l0, h1, l1;
                split2(v0, h0, l0);
                split2(v1, h1, l1);
                *(__half2*)(Ch + (size_t)rbase * ldc + ccol) = __halves2half2(h0, h1);
                *(__half2*)(Cl + (size_t)rbase * ldc + ccol) = __halves2half2(l0, l1);
                split2(v2, h0, l0);
                split2(v3, h1, l1);
                *(__half2*)(Ch + (size_t)(rbase + 8) * ldc + ccol) = __halves2half2(h0, h1);
                *(__half2*)(Cl + (size_t)(rbase + 8) * ldc + ccol) = __halves2half2(l0, l1);
            } else {
                *(__half2*)(Ch + (size_t)rbase * ldc + ccol) =
                    __halves2half2(__float2half_rn(v0), __float2half_rn(v1));
                *(__half2*)(Ch + (size_t)(rbase + 8) * ldc + ccol) =
                    __halves2half2(__float2half_rn(v2), __float2half_rn(v3));
            }
        }
    }
}

// ---------------- prep kernels ----------------
__global__ void split_x_kernel(const float* __restrict__ x) {
    const int n = 8192 * 1024;
    for (int i = blockIdx.x * blockDim.x + threadIdx.x; i < n; i += gridDim.x * blockDim.x)
        g_xh[i] = __float2half_rn(x[i]);
}

__global__ void wt_kernel(const float* __restrict__ Wq, const float* __restrict__ Wk,
                          const float* __restrict__ Wv) {
    __shared__ float t[32][33];
    const float* W = (blockIdx.z == 0) ? Wq : (blockIdx.z == 1) ? Wk : Wv;
    __half* Th = g_WTh + (size_t)blockIdx.z * 1024 * 1024;
    __half* Tl = g_WTl + (size_t)blockIdx.z * 1024 * 1024;
    const int n0 = blockIdx.x * 32, k0 = blockIdx.y * 32;
    const int tx = threadIdx.x, ty = threadIdx.y;
#pragma unroll
    for (int i = 0; i < 4; ++i)
        t[ty + i * 8][tx] = W[(size_t)(k0 + ty + i * 8) * 1024 + n0 + tx];
    __syncthreads();
#pragma unroll
    for (int i = 0; i < 4; ++i) {
        __half h, l;
        split2(t[tx][ty + i * 8], h, l);  // = W[k0+tx][n0+ty+i*8]
        const size_t o = (size_t)(n0 + ty + i * 8) * 1024 + k0 + tx;
        Th[o] = h; Tl[o] = l;
    }
}

__global__ void vt_kernel() {
    __shared__ float t[32][33];
    const int b = blockIdx.z;
    const float* V = g_V + (size_t)b * 2048 * 1024;
    __half* Th = g_VTh + (size_t)b * 1024 * 2048;
    __half* Tl = g_VTl + (size_t)b * 1024 * 2048;
    const int e0 = blockIdx.x * 32, k0 = blockIdx.y * 32;
    const int tx = threadIdx.x, ty = threadIdx.y;
#pragma unroll
    for (int i = 0; i < 4; ++i)
        t[ty + i * 8][tx] = V[(size_t)(k0 + ty + i * 8) * 1024 + e0 + tx];
    __syncthreads();
#pragma unroll
    for (int i = 0; i < 4; ++i) {
        __half h, l;
        split2(t[tx][ty + i * 8], h, l);  // = V[k0+tx][e0+ty+i*8]
        const size_t o = (size_t)(e0 + ty + i * 8) * 2048 + k0 + tx;
        Th[o] = h; Tl[o] = l;
    }
}

// ---------------- GEMM kernels ----------------
__global__ void __launch_bounds__(TPB, 1)
proj_kernel() {
    const int z = blockIdx.z;
    const int m0 = blockIdx.y * 128;
    const int n0 = blockIdx.x * 128;
    const __half* Bh = g_WTh + (size_t)z * 1024 * 1024;
    const __half* Bl = g_WTl + (size_t)z * 1024 * 1024;
    if (z == 0)       // Q used only as A downstream -> fp16 hi only
        gemm_core<2>(g_xh, 1024, Bh, Bl, 1024, m0, n0, 1024, 1.0f,
                     nullptr, g_Qh, nullptr, 1024);
    else if (z == 1)  // K used as B downstream -> split
        gemm_core<1>(g_xh, 1024, Bh, Bl, 1024, m0, n0, 1024, 1.0f,
                     nullptr, g_Kh, g_Kl, 1024);
    else              // V -> fp32, then transposed+split
        gemm_core<0>(g_xh, 1024, Bh, Bl, 1024, m0, n0, 1024, 1.0f,
                     g_V, nullptr, nullptr, 1024);
}

__global__ void __launch_bounds__(TPB, 1)
score_kernel() {
    const int kb = blockIdx.x, qb = blockIdx.y, b = blockIdx.z;
    if (kb > qb) return;
    const size_t qo = (size_t)b * 2048 * 1024;
    gemm_core<0>(g_Qh + qo, 1024, g_Kh + qo, g_Kl + qo, 1024,
                 qb * 128, kb * 128, 1024, 0.03125f,
                 g_S + (size_t)b * 2048 * 2048, nullptr, nullptr, 2048);
}

__global__ void __launch_bounds__(TPB, 1)
pv_kernel(float* __restrict__ out) {
    const int nb = blockIdx.x, qb = blockIdx.y, b = blockIdx.z;
    const size_t po = (size_t)b * 2048 * 2048;
    const size_t vo = (size_t)b * 1024 * 2048;
    gemm_core<0>(g_Ph + po, 2048, g_VTh + vo, g_VTl + vo, 2048,
                 qb * 128, nb * 128, (qb + 1) * 128, 1.0f,
                 out + (size_t)b * 2048 * 1024, nullptr, nullptr, 1024);
}

// ---------------- softmax ----------------
__global__ void softmax_kernel() {
    const int q = blockIdx.x, b = blockIdx.y;
    float* row = g_S + ((size_t)b * 2048 + q) * 2048;
    __half* ph = g_Ph + ((size_t)b * 2048 + q) * 2048;
    const int len = q + 1;
    const int tid = threadIdx.x;
    __shared__ float red[TPB];

    float m = -1e30f;
    for (int i = tid; i < len; i += TPB) m = fmaxf(m, row[i]);
    red[tid] = m;
    __syncthreads();
#pragma unroll
    for (int s = TPB / 2; s > 0; s >>= 1) {
        if (tid < s) red[tid] = fmaxf(red[tid], red[tid + s]);
        __syncthreads();
    }
    m = red[0];
    __syncthreads();

    float sum = 0.0f;
    for (int i = tid; i < len; i += TPB) {
        float e = __expf(row[i] - m);
        row[i] = e;
        sum += e;
    }
    red[tid] = sum;
    __syncthreads();
#pragma unroll
    for (int s = TPB / 2; s > 0; s >>= 1) {
        if (tid < s) red[tid] += red[tid + s];
        __syncthreads();
    }
    const float inv = 1.0f / red[0];
    __syncthreads();

    const __half z = __float2half(0.0f);
    for (int i = tid; i < len; i += TPB)
        ph[i] = __float2half_rn(row[i] * inv);
    const int klim = ((q >> 7) + 1) << 7;  // zero up to 128-tile boundary
    for (int i = len + tid; i < klim; i += TPB) ph[i] = z;
}

// ---------------- launch ----------------
extern "C" void kernel_launch(void* const* d_in, const int* in_sizes, int n_in,
                              void* d_out, int out_size) {
    const float* x  = (const float*)d_in[0];
    const float* Wq = (const float*)d_in[1];
    const float* Wk = (const float*)d_in[2];
    const float* Wv = (const float*)d_in[3];
    float* out = (float*)d_out;

    cudaFuncSetAttribute(proj_kernel,  cudaFuncAttributeMaxDynamicSharedMemorySize, GEMM_SMEM);
    cudaFuncSetAttribute(score_kernel, cudaFuncAttributeMaxDynamicSharedMemorySize, GEMM_SMEM);
    cudaFuncSetAttribute(pv_kernel,    cudaFuncAttributeMaxDynamicSharedMemorySize, GEMM_SMEM);

    split_x_kernel<<<4096, 256>>>(x);
    wt_kernel<<<dim3(32, 32, 3), dim3(32, 8)>>>(Wq, Wk, Wv);
    proj_kernel<<<dim3(8, 64, 3), TPB, GEMM_SMEM>>>();
    vt_kernel<<<dim3(32, 64, 4), dim3(32, 8)>>>();
    score_kernel<<<dim3(16, 16, 4), TPB, GEMM_SMEM>>>();
    softmax_kernel<<<dim3(2048, 4), TPB>>>();
    pv_kernel<<<dim3(8, 16, 4), TPB, GEMM_SMEM>>>(out);
}